// round 2
// baseline (speedup 1.0000x reference)
#include <cuda_runtime.h>
#include <cstdint>
#include <cstddef>

#define EPSV 1e-8f

// Gate pre-activations scratch: [B=4][S=2048][4 gates][NH=4][HD=256] fp32 = 128 MiB
static __device__ float g_gates[33554432];

// ---------------------------------------------------------------------------
// packed f32x2 helpers (FFMA2 path — PTX-only on sm_103a)
// ---------------------------------------------------------------------------
__device__ __forceinline__ unsigned long long pk2(float lo, float hi) {
    unsigned long long r;
    asm("mov.b64 %0, {%1,%2};" : "=l"(r) : "f"(lo), "f"(hi));
    return r;
}
__device__ __forceinline__ unsigned long long ffma2(unsigned long long a,
                                                    unsigned long long b,
                                                    unsigned long long c) {
    unsigned long long d;
    asm("fma.rn.f32x2 %0, %1, %2, %3;" : "=l"(d) : "l"(a), "l"(b), "l"(c));
    return d;
}
__device__ __forceinline__ float2 upk2(unsigned long long v) {
    float lo, hi;
    asm("mov.b64 {%0,%1}, %2;" : "=f"(lo), "=f"(hi) : "l"(v));
    return make_float2(lo, hi);
}

// ---------------------------------------------------------------------------
// Kernel 1: block-diagonal GEMM + bias
//   gates[m][gh*256 + n] = sum_k X[m][gh*256 + k] * W[gh][n][k] + bias[gh][n]
//   M = B*S = 8192 rows. grid = (64 M-tiles, 32 = 16 gh * 2 n-halves), 256 thr.
//   128x128 tile, K-chunk 16, double-buffered smem, f32x2 accumulators.
// ---------------------------------------------------------------------------
__global__ __launch_bounds__(256) void gemm_gates_kernel(
    const float* __restrict__ X, const float* __restrict__ W,
    const float* __restrict__ Bias)
{
    __shared__ float As[2][16][132];
    __shared__ float Bs[2][16][132];

    const int t  = threadIdx.x;
    const int bx = blockIdx.x;          // M tile (128 rows)
    const int by = blockIdx.y;          // gh*2 + nhalf
    const int gh = by >> 1;
    const int nh = (by & 1) << 7;       // 0 or 128
    const int tx = t & 15, ty = t >> 4; // 16x16 thread grid, 8x8 microtile

    const float* Abase = X + (size_t)bx * 128 * 4096 + gh * 256;
    const float* Bbase = W + (size_t)gh * 65536 + (size_t)nh * 256;

    // each thread loads two float4 per chunk for A and two for B
    const int m0g = t >> 2,          k0g = (t & 3) << 2;        // f = t
    const int m1g = (t + 256) >> 2,  k1g = ((t + 256) & 3) << 2; // f = t+256

    float4 ra0 = *(const float4*)(Abase + (size_t)m0g * 4096 + k0g);
    float4 ra1 = *(const float4*)(Abase + (size_t)m1g * 4096 + k1g);
    float4 rb0 = *(const float4*)(Bbase + (size_t)m0g * 256  + k0g);
    float4 rb1 = *(const float4*)(Bbase + (size_t)m1g * 256  + k1g);

    unsigned long long acc[8][4];
#pragma unroll
    for (int i = 0; i < 8; ++i)
#pragma unroll
        for (int p = 0; p < 4; ++p) acc[i][p] = 0ull;  // (+0.f, +0.f)

    // store chunk 0 (transposed to k-major)
    As[0][k0g+0][m0g]=ra0.x; As[0][k0g+1][m0g]=ra0.y; As[0][k0g+2][m0g]=ra0.z; As[0][k0g+3][m0g]=ra0.w;
    As[0][k1g+0][m1g]=ra1.x; As[0][k1g+1][m1g]=ra1.y; As[0][k1g+2][m1g]=ra1.z; As[0][k1g+3][m1g]=ra1.w;
    Bs[0][k0g+0][m0g]=rb0.x; Bs[0][k0g+1][m0g]=rb0.y; Bs[0][k0g+2][m0g]=rb0.z; Bs[0][k0g+3][m0g]=rb0.w;
    Bs[0][k1g+0][m1g]=rb1.x; Bs[0][k1g+1][m1g]=rb1.y; Bs[0][k1g+2][m1g]=rb1.z; Bs[0][k1g+3][m1g]=rb1.w;
    __syncthreads();

    int cur = 0;
#pragma unroll 1
    for (int kt = 0; kt < 16; ++kt) {
        if (kt < 15) {
            const int k0 = (kt + 1) * 16;
            ra0 = *(const float4*)(Abase + (size_t)m0g * 4096 + k0 + k0g);
            ra1 = *(const float4*)(Abase + (size_t)m1g * 4096 + k0 + k1g);
            rb0 = *(const float4*)(Bbase + (size_t)m0g * 256  + k0 + k0g);
            rb1 = *(const float4*)(Bbase + (size_t)m1g * 256  + k0 + k1g);
        }
#pragma unroll
        for (int kk = 0; kk < 16; ++kk) {
            float4 a0 = *(const float4*)&As[cur][kk][ty * 4];
            float4 a1 = *(const float4*)&As[cur][kk][64 + ty * 4];
            float4 b0 = *(const float4*)&Bs[cur][kk][tx * 4];
            float4 b1 = *(const float4*)&Bs[cur][kk][64 + tx * 4];
            unsigned long long bp0 = pk2(b0.x, b0.y), bp1 = pk2(b0.z, b0.w);
            unsigned long long bp2 = pk2(b1.x, b1.y), bp3 = pk2(b1.z, b1.w);
            float av[8] = {a0.x, a0.y, a0.z, a0.w, a1.x, a1.y, a1.z, a1.w};
#pragma unroll
            for (int i = 0; i < 8; ++i) {
                unsigned long long ap = pk2(av[i], av[i]);
                acc[i][0] = ffma2(ap, bp0, acc[i][0]);
                acc[i][1] = ffma2(ap, bp1, acc[i][1]);
                acc[i][2] = ffma2(ap, bp2, acc[i][2]);
                acc[i][3] = ffma2(ap, bp3, acc[i][3]);
            }
        }
        if (kt < 15) {
            cur ^= 1;
            As[cur][k0g+0][m0g]=ra0.x; As[cur][k0g+1][m0g]=ra0.y; As[cur][k0g+2][m0g]=ra0.z; As[cur][k0g+3][m0g]=ra0.w;
            As[cur][k1g+0][m1g]=ra1.x; As[cur][k1g+1][m1g]=ra1.y; As[cur][k1g+2][m1g]=ra1.z; As[cur][k1g+3][m1g]=ra1.w;
            Bs[cur][k0g+0][m0g]=rb0.x; Bs[cur][k0g+1][m0g]=rb0.y; Bs[cur][k0g+2][m0g]=rb0.z; Bs[cur][k0g+3][m0g]=rb0.w;
            Bs[cur][k1g+0][m1g]=rb1.x; Bs[cur][k1g+1][m1g]=rb1.y; Bs[cur][k1g+2][m1g]=rb1.z; Bs[cur][k1g+3][m1g]=rb1.w;
            __syncthreads();
        }
    }

    // epilogue: bias + store
    const float* bb = Bias + gh * 256 + nh;
    float4 bv0 = *(const float4*)(bb + tx * 4);
    float4 bv1 = *(const float4*)(bb + 64 + tx * 4);
    float bl[8] = {bv0.x, bv0.y, bv0.z, bv0.w, bv1.x, bv1.y, bv1.z, bv1.w};

#pragma unroll
    for (int i = 0; i < 8; ++i) {
        const int m = (i < 4) ? (ty * 4 + i) : (64 + ty * 4 + (i - 4));
        float* orow = g_gates + (size_t)(bx * 128 + m) * 4096 + gh * 256 + nh;
        float2 v0 = upk2(acc[i][0]);
        float2 v1 = upk2(acc[i][1]);
        float2 v2 = upk2(acc[i][2]);
        float2 v3 = upk2(acc[i][3]);
        float4 w0 = make_float4(v0.x + bl[0], v0.y + bl[1], v1.x + bl[2], v1.y + bl[3]);
        float4 w1 = make_float4(v2.x + bl[4], v2.y + bl[5], v3.x + bl[6], v3.y + bl[7]);
        *(float4*)(orow + tx * 4)      = w0;
        *(float4*)(orow + 64 + tx * 4) = w1;
    }
}

// ---------------------------------------------------------------------------
// Kernel 2: sLSTM scan. 4096 independent channels (b,h,d), serial over S=2048.
// 32 blocks x 128 threads -> 1 warp per SMSP on 32 SMs (MUFU-optimal).
// Output buffer layout: [h_seq (B,S,NH,HD)] [h_f] [c_f] [n_f] [m_f]
// ---------------------------------------------------------------------------
__global__ __launch_bounds__(128) void slstm_scan_kernel(float* __restrict__ Out)
{
    const int ch = blockIdx.x * blockDim.x + threadIdx.x;  // 0..4095
    const int b  = ch >> 10;
    const int hd = ch & 1023;                              // h*256 + d
    const float* gp = g_gates + (size_t)b * 2048 * 4096 + hd;
    float* hp = Out + (size_t)b * 2048 * 1024 + hd;

    float c = 0.f, n = 0.f, m = 0.f, hv = 0.f;

#pragma unroll 8
    for (int s = 0; s < 2048; ++s) {
        const float* row = gp + (size_t)s * 4096;
        float zb = __ldg(row);
        float ib = __ldg(row + 1024);
        float fb = __ldg(row + 2048);
        float ob = __ldg(row + 3072);

        // tanh(z) = 1 - 2/(e^{2z}+1); sigmoid(o) = 1/(1+e^{-o})
        float zv = 1.f - __fdividef(2.f, __expf(2.f * zb) + 1.f);
        float ov = __fdividef(1.f, 1.f + __expf(-ob));

        // log(exp(g) + 1e-8) == g to <4e-6 abs for g > -6; exact path for the tail
        float lf = fb, li = ib;
        if (fminf(fb, ib) < -6.f) {
            lf = __logf(__expf(fb) + EPSV);
            li = __logf(__expf(ib) + EPSV);
        }

        float mn = fmaxf(lf + m, li);
        float ih = __expf(li - mn);
        float fh = __expf(lf + m - mn);
        c = fmaf(fh, c, ih * zv);
        n = fmaf(fh, n, ih);
        m = mn;
        hv = ov * __fdividef(c, n + EPSV);
        hp[(size_t)s * 1024] = hv;
    }

    // final states: each [B, NH, HD] flat index == ch
    Out[8388608 + ch]         = hv;  // h_f
    Out[8388608 + 4096 + ch]  = c;   // c_f
    Out[8388608 + 8192 + ch]  = n;   // n_f
    Out[8388608 + 12288 + ch] = m;   // m_f
}

// ---------------------------------------------------------------------------
extern "C" void kernel_launch(void* const* d_in, const int* in_sizes, int n_in,
                              void* d_out, int out_size)
{
    const float* X  = (const float*)d_in[0];  // [4, 2048, 4096]
    const float* W  = (const float*)d_in[1];  // [4, 4, 256, 256]
    const float* Bv = (const float*)d_in[2];  // [4, 4, 256]
    float* out = (float*)d_out;

    gemm_gates_kernel<<<dim3(64, 32), 256>>>(X, W, Bv);
    slstm_scan_kernel<<<32, 128>>>(out);
}

// round 4
// speedup vs baseline: 1.3926x; 1.3926x over previous
#include <cuda_runtime.h>
#include <cstdint>
#include <cstddef>

#define EPSV 1e-8f
#define CHUNK 16
#define NCHUNK 128
#define NCH 4096  // channels = B*NH*HD

// Gate pre-activations scratch: [B=4][S=2048][4 gates][NH=4][HD=256] fp32 = 128 MiB
static __device__ float g_gates[33554432];
// per-(chunk,channel) local state (F, m_loc, c_loc, n_loc)
static __device__ float4 g_cstate[NCHUNK * NCH];
// per-(chunk,channel) carry-in state (m, c, n, -)
static __device__ float4 g_carry[NCHUNK * NCH];

// ---------------------------------------------------------------------------
// packed f32x2 helpers (FFMA2 path — PTX-only on sm_103a)
// ---------------------------------------------------------------------------
__device__ __forceinline__ unsigned long long pk2(float lo, float hi) {
    unsigned long long r;
    asm("mov.b64 %0, {%1,%2};" : "=l"(r) : "f"(lo), "f"(hi));
    return r;
}
__device__ __forceinline__ unsigned long long ffma2(unsigned long long a,
                                                    unsigned long long b,
                                                    unsigned long long c) {
    unsigned long long d;
    asm("fma.rn.f32x2 %0, %1, %2, %3;" : "=l"(d) : "l"(a), "l"(b), "l"(c));
    return d;
}
__device__ __forceinline__ float2 upk2(unsigned long long v) {
    float lo, hi;
    asm("mov.b64 {%0,%1}, %2;" : "=f"(lo), "=f"(hi) : "l"(v));
    return make_float2(lo, hi);
}

// ---------------------------------------------------------------------------
// Kernel 1: block-diagonal GEMM + bias  (unchanged from R1; ~305us)
// ---------------------------------------------------------------------------
__global__ __launch_bounds__(256) void gemm_gates_kernel(
    const float* __restrict__ X, const float* __restrict__ W,
    const float* __restrict__ Bias)
{
    __shared__ float As[2][16][132];
    __shared__ float Bs[2][16][132];

    const int t  = threadIdx.x;
    const int bx = blockIdx.x;          // M tile (128 rows)
    const int by = blockIdx.y;          // gh*2 + nhalf
    const int gh = by >> 1;
    const int nh = (by & 1) << 7;       // 0 or 128
    const int tx = t & 15, ty = t >> 4; // 16x16 thread grid, 8x8 microtile

    const float* Abase = X + (size_t)bx * 128 * 4096 + gh * 256;
    const float* Bbase = W + (size_t)gh * 65536 + (size_t)nh * 256;

    const int m0g = t >> 2,          k0g = (t & 3) << 2;
    const int m1g = (t + 256) >> 2,  k1g = ((t + 256) & 3) << 2;

    float4 ra0 = *(const float4*)(Abase + (size_t)m0g * 4096 + k0g);
    float4 ra1 = *(const float4*)(Abase + (size_t)m1g * 4096 + k1g);
    float4 rb0 = *(const float4*)(Bbase + (size_t)m0g * 256  + k0g);
    float4 rb1 = *(const float4*)(Bbase + (size_t)m1g * 256  + k1g);

    unsigned long long acc[8][4];
#pragma unroll
    for (int i = 0; i < 8; ++i)
#pragma unroll
        for (int p = 0; p < 4; ++p) acc[i][p] = 0ull;

    As[0][k0g+0][m0g]=ra0.x; As[0][k0g+1][m0g]=ra0.y; As[0][k0g+2][m0g]=ra0.z; As[0][k0g+3][m0g]=ra0.w;
    As[0][k1g+0][m1g]=ra1.x; As[0][k1g+1][m1g]=ra1.y; As[0][k1g+2][m1g]=ra1.z; As[0][k1g+3][m1g]=ra1.w;
    Bs[0][k0g+0][m0g]=rb0.x; Bs[0][k0g+1][m0g]=rb0.y; Bs[0][k0g+2][m0g]=rb0.z; Bs[0][k0g+3][m0g]=rb0.w;
    Bs[0][k1g+0][m1g]=rb1.x; Bs[0][k1g+1][m1g]=rb1.y; Bs[0][k1g+2][m1g]=rb1.z; Bs[0][k1g+3][m1g]=rb1.w;
    __syncthreads();

    int cur = 0;
#pragma unroll 1
    for (int kt = 0; kt < 16; ++kt) {
        if (kt < 15) {
            const int k0 = (kt + 1) * 16;
            ra0 = *(const float4*)(Abase + (size_t)m0g * 4096 + k0 + k0g);
            ra1 = *(const float4*)(Abase + (size_t)m1g * 4096 + k0 + k1g);
            rb0 = *(const float4*)(Bbase + (size_t)m0g * 256  + k0 + k0g);
            rb1 = *(const float4*)(Bbase + (size_t)m1g * 256  + k0 + k1g);
        }
#pragma unroll
        for (int kk = 0; kk < 16; ++kk) {
            float4 a0 = *(const float4*)&As[cur][kk][ty * 4];
            float4 a1 = *(const float4*)&As[cur][kk][64 + ty * 4];
            float4 b0 = *(const float4*)&Bs[cur][kk][tx * 4];
            float4 b1 = *(const float4*)&Bs[cur][kk][64 + tx * 4];
            unsigned long long bp0 = pk2(b0.x, b0.y), bp1 = pk2(b0.z, b0.w);
            unsigned long long bp2 = pk2(b1.x, b1.y), bp3 = pk2(b1.z, b1.w);
            float av[8] = {a0.x, a0.y, a0.z, a0.w, a1.x, a1.y, a1.z, a1.w};
#pragma unroll
            for (int i = 0; i < 8; ++i) {
                unsigned long long ap = pk2(av[i], av[i]);
                acc[i][0] = ffma2(ap, bp0, acc[i][0]);
                acc[i][1] = ffma2(ap, bp1, acc[i][1]);
                acc[i][2] = ffma2(ap, bp2, acc[i][2]);
                acc[i][3] = ffma2(ap, bp3, acc[i][3]);
            }
        }
        if (kt < 15) {
            cur ^= 1;
            As[cur][k0g+0][m0g]=ra0.x; As[cur][k0g+1][m0g]=ra0.y; As[cur][k0g+2][m0g]=ra0.z; As[cur][k0g+3][m0g]=ra0.w;
            As[cur][k1g+0][m1g]=ra1.x; As[cur][k1g+1][m1g]=ra1.y; As[cur][k1g+2][m1g]=ra1.z; As[cur][k1g+3][m1g]=ra1.w;
            Bs[cur][k0g+0][m0g]=rb0.x; Bs[cur][k0g+1][m0g]=rb0.y; Bs[cur][k0g+2][m0g]=rb0.z; Bs[cur][k0g+3][m0g]=rb0.w;
            Bs[cur][k1g+0][m1g]=rb1.x; Bs[cur][k1g+1][m1g]=rb1.y; Bs[cur][k1g+2][m1g]=rb1.z; Bs[cur][k1g+3][m1g]=rb1.w;
            __syncthreads();
        }
    }

    const float* bb = Bias + gh * 256 + nh;
    float4 bv0 = *(const float4*)(bb + tx * 4);
    float4 bv1 = *(const float4*)(bb + 64 + tx * 4);
    float bl[8] = {bv0.x, bv0.y, bv0.z, bv0.w, bv1.x, bv1.y, bv1.z, bv1.w};

#pragma unroll
    for (int i = 0; i < 8; ++i) {
        const int m = (i < 4) ? (ty * 4 + i) : (64 + ty * 4 + (i - 4));
        float* orow = g_gates + (size_t)(bx * 128 + m) * 4096 + gh * 256 + nh;
        float2 v0 = upk2(acc[i][0]);
        float2 v1 = upk2(acc[i][1]);
        float2 v2 = upk2(acc[i][2]);
        float2 v3 = upk2(acc[i][3]);
        float4 w0 = make_float4(v0.x + bl[0], v0.y + bl[1], v1.x + bl[2], v1.y + bl[3]);
        float4 w1 = make_float4(v2.x + bl[4], v2.y + bl[5], v3.x + bl[6], v3.y + bl[7]);
        *(float4*)(orow + tx * 4)      = w0;
        *(float4*)(orow + 64 + tx * 4) = w1;
    }
}

// ---------------------------------------------------------------------------
// Scan phase 1: per-(channel, chunk) local reduction.
// grid (16, NCHUNK) x 256 threads; thread = (channel, chunk).
// Computes F = sum(lf), and local (m,c,n) starting from m=-inf, c=n=0.
// ---------------------------------------------------------------------------
__global__ __launch_bounds__(256) void scan_local_kernel()
{
    const int ch = blockIdx.x * 256 + threadIdx.x;  // 0..4095
    const int k  = blockIdx.y;                      // chunk
    const int b  = ch >> 10;
    const int hd = ch & 1023;
    const float* gp = g_gates + (size_t)b * 2048 * 4096 + (size_t)k * CHUNK * 4096 + hd;

    float m = -1e30f, c = 0.f, n = 0.f, F = 0.f;

#pragma unroll
    for (int s = 0; s < CHUNK; ++s) {
        const float* row = gp + (size_t)s * 4096;
        float zb = __ldg(row);
        float ib = __ldg(row + 1024);
        float fb = __ldg(row + 2048);

        float zv = 1.f - __fdividef(2.f, __expf(2.f * zb) + 1.f);

        float lf = fb, li = ib;
        if (fminf(fb, ib) < -6.f) {
            lf = __logf(__expf(fb) + EPSV);
            li = __logf(__expf(ib) + EPSV);
        }
        F += lf;

        float mn = fmaxf(lf + m, li);
        float ih = __expf(li - mn);
        float fh = __expf(lf + m - mn);
        c = fmaf(fh, c, ih * zv);
        n = fmaf(fh, n, ih);
        m = mn;
    }
    g_cstate[(size_t)k * NCH + ch] = make_float4(F, m, c, n);
}

// ---------------------------------------------------------------------------
// Scan phase 2: sequential combine over chunks per channel (exact).
// Also writes final c_f, n_f, m_f.
// ---------------------------------------------------------------------------
__global__ __launch_bounds__(256) void scan_combine_kernel(float* __restrict__ Out)
{
    const int ch = blockIdx.x * 256 + threadIdx.x;  // 0..4095
    float m = 0.f, c = 0.f, n = 0.f;                // reference initial state

#pragma unroll 4
    for (int k = 0; k < NCHUNK; ++k) {
        g_carry[(size_t)k * NCH + ch] = make_float4(m, c, n, 0.f);
        float4 st = g_cstate[(size_t)k * NCH + ch];  // (F, m_loc, c_loc, n_loc)
        float mo = fmaxf(st.x + m, st.y);
        float ea = __expf(st.x + m - mo);
        float eb = __expf(st.y - mo);
        c = fmaf(ea, c, eb * st.z);
        n = fmaf(ea, n, eb * st.w);
        m = mo;
    }
    Out[8388608 + 4096 + ch]  = c;   // c_f
    Out[8388608 + 8192 + ch]  = n;   // n_f
    Out[8388608 + 12288 + ch] = m;   // m_f
}

// ---------------------------------------------------------------------------
// Scan phase 3: replay each chunk from its exact carry-in and emit h.
// grid (16, NCHUNK) x 256 threads.
// ---------------------------------------------------------------------------
__global__ __launch_bounds__(256) void scan_emit_kernel(float* __restrict__ Out)
{
    const int ch = blockIdx.x * 256 + threadIdx.x;
    const int k  = blockIdx.y;
    const int b  = ch >> 10;
    const int hd = ch & 1023;
    const float* gp = g_gates + (size_t)b * 2048 * 4096 + (size_t)k * CHUNK * 4096 + hd;
    float* hp = Out + (size_t)b * 2048 * 1024 + (size_t)k * CHUNK * 1024 + hd;

    float4 cr = g_carry[(size_t)k * NCH + ch];
    float m = cr.x, c = cr.y, n = cr.z, hv = 0.f;

#pragma unroll
    for (int s = 0; s < CHUNK; ++s) {
        const float* row = gp + (size_t)s * 4096;
        float zb = __ldg(row);
        float ib = __ldg(row + 1024);
        float fb = __ldg(row + 2048);
        float ob = __ldg(row + 3072);

        float zv = 1.f - __fdividef(2.f, __expf(2.f * zb) + 1.f);
        float ov = __fdividef(1.f, 1.f + __expf(-ob));

        float lf = fb, li = ib;
        if (fminf(fb, ib) < -6.f) {
            lf = __logf(__expf(fb) + EPSV);
            li = __logf(__expf(ib) + EPSV);
        }

        float mn = fmaxf(lf + m, li);
        float ih = __expf(li - mn);
        float fh = __expf(lf + m - mn);
        c = fmaf(fh, c, ih * zv);
        n = fmaf(fh, n, ih);
        m = mn;
        hv = ov * __fdividef(c, n + EPSV);
        hp[(size_t)s * 1024] = hv;
    }

    if (k == NCHUNK - 1) Out[8388608 + ch] = hv;  // h_f
}

// ---------------------------------------------------------------------------
extern "C" void kernel_launch(void* const* d_in, const int* in_sizes, int n_in,
                              void* d_out, int out_size)
{
    const float* X  = (const float*)d_in[0];  // [4, 2048, 4096]
    const float* W  = (const float*)d_in[1];  // [4, 4, 256, 256]
    const float* Bv = (const float*)d_in[2];  // [4, 4, 256]
    float* out = (float*)d_out;

    gemm_gates_kernel<<<dim3(64, 32), 256>>>(X, W, Bv);
    scan_local_kernel<<<dim3(16, NCHUNK), 256>>>();
    scan_combine_kernel<<<16, 256>>>(out);
    scan_emit_kernel<<<dim3(16, NCHUNK), 256>>>(out);
}

// round 6
// speedup vs baseline: 2.8414x; 2.0404x over previous
#include <cuda_runtime.h>
#include <cuda_bf16.h>
#include <cstdint>
#include <cstddef>

#define EPSV 1e-8f
#define CHUNK 16
#define NCHUNK 128
#define NCH 4096  // channels = B*NH*HD

// Gate pre-activations scratch: [B=4][S=2048][4 gates][NH=4][HD=256] fp32 = 128 MiB
static __device__ float g_gates[33554432];
// per-(chunk,channel) local state (F, m_loc, c_loc, n_loc)
static __device__ float4 g_cstate[NCHUNK * NCH];
// per-(chunk,channel) carry-in state (m, c, n, -)
static __device__ float4 g_carry[NCHUNK * NCH];
// Pre-split weights: bf16 hi/lo, layout [gh][n][k] like W
static __device__ __nv_bfloat16 g_W0[1048576];
static __device__ __nv_bfloat16 g_W1[1048576];

// ---------------------------------------------------------------------------
__device__ __forceinline__ uint32_t smem_u32(const void* p) {
    uint32_t a;
    asm("{ .reg .u64 t; cvta.to.shared.u64 t, %1; cvt.u32.u64 %0, t; }" : "=r"(a) : "l"(p));
    return a;
}
__device__ __forceinline__ void ldsm4(uint32_t* r, uint32_t addr) {
    asm volatile("ldmatrix.sync.aligned.m8n8.x4.shared.b16 {%0,%1,%2,%3}, [%4];"
                 : "=r"(r[0]), "=r"(r[1]), "=r"(r[2]), "=r"(r[3]) : "r"(addr));
}
__device__ __forceinline__ void mma16816(float* c, const uint32_t* a, const uint32_t* b) {
    asm volatile(
        "mma.sync.aligned.m16n8k16.row.col.f32.bf16.bf16.f32 "
        "{%0,%1,%2,%3}, {%4,%5,%6,%7}, {%8,%9}, {%0,%1,%2,%3};"
        : "+f"(c[0]), "+f"(c[1]), "+f"(c[2]), "+f"(c[3])
        : "r"(a[0]), "r"(a[1]), "r"(a[2]), "r"(a[3]), "r"(b[0]), "r"(b[1]));
}

// ===========================================================================
// Kernel 0: pre-split W (fp32 -> bf16 hi + bf16 lo). 1,048,576 elements.
// ===========================================================================
__global__ __launch_bounds__(256) void wsplit_kernel(const float* __restrict__ W)
{
    const int i = blockIdx.x * 256 + threadIdx.x;  // float4 id, 262144 total
    float4 v = *(const float4*)(W + (size_t)i * 4);
    __nv_bfloat162 h0 = __floats2bfloat162_rn(v.x, v.y);
    __nv_bfloat162 h1 = __floats2bfloat162_rn(v.z, v.w);
    float2 r0 = make_float2(v.x - __bfloat162float(h0.x), v.y - __bfloat162float(h0.y));
    float2 r1 = make_float2(v.z - __bfloat162float(h1.x), v.w - __bfloat162float(h1.y));
    __nv_bfloat162 l0 = __floats2bfloat162_rn(r0.x, r0.y);
    __nv_bfloat162 l1 = __floats2bfloat162_rn(r1.x, r1.y);
    uint2 uh, ul;
    uh.x = *(const uint32_t*)&h0; uh.y = *(const uint32_t*)&h1;
    ul.x = *(const uint32_t*)&l0; ul.y = *(const uint32_t*)&l1;
    *(uint2*)&g_W0[(size_t)i * 4] = uh;
    *(uint2*)&g_W1[(size_t)i * 4] = ul;
}

// ===========================================================================
// Kernel 1: block-diagonal GEMM via mma.sync bf16 (3-term 2-split)
//   grid (64 m-tiles, 16 gh), 512 threads = 16 warps (2 m x 8 n),
//   warp tile 64x32. K=256 in 16 chunks of 16.
//   smem rows: 16 bf16 data + 8 pad = 48B row pitch (conflict-free ldmatrix).
// ===========================================================================
#define APITCH 48       // bytes per A/B smem row (16 bf16 + 8 pad)
#define SA0 0           // 128 rows * 48B = 6144
#define SA1 6144
#define SB0 12288       // 256 rows * 48B = 12288
#define SB1 24576
#define SMEM_GEMM 36864

__global__ __launch_bounds__(512) void gemm_mma_kernel(
    const float* __restrict__ X, const float* __restrict__ Bias)
{
    __shared__ __align__(16) char smem[SMEM_GEMM];
    const uint32_t sb = smem_u32(smem);

    const int tid  = threadIdx.x;
    const int lane = tid & 31;
    const int wid  = tid >> 5;
    const int wm   = (wid & 1) * 64;   // warp m offset
    const int wn   = (wid >> 1) * 32;  // warp n offset
    const int bx   = blockIdx.x;
    const int gh   = blockIdx.y;

    float c[4][4][4];
#pragma unroll
    for (int i = 0; i < 4; ++i)
#pragma unroll
        for (int j = 0; j < 4; ++j)
#pragma unroll
            for (int q = 0; q < 4; ++q) c[i][j][q] = 0.f;

    // staging pointers (per-thread)
    const float* xp = X + (size_t)(bx * 128 + (tid >> 2)) * 4096 + gh * 256 + (tid & 3) * 4;
    const __nv_bfloat16* w0p = g_W0 + (size_t)gh * 65536 + (size_t)(tid >> 1) * 256 + (tid & 1) * 8;
    const __nv_bfloat16* w1p = g_W1 + (size_t)gh * 65536 + (size_t)(tid >> 1) * 256 + (tid & 1) * 8;

    char* a0s = smem + SA0 + (tid >> 2) * APITCH + (tid & 3) * 8;
    char* a1s = smem + SA1 + (tid >> 2) * APITCH + (tid & 3) * 8;
    char* b0s = smem + SB0 + (tid >> 1) * APITCH + (tid & 1) * 16;
    char* b1s = smem + SB1 + (tid >> 1) * APITCH + (tid & 1) * 16;

    // ldmatrix base addresses
    const uint32_t aRow = sb + SA0 + (uint32_t)(wm + (lane & 15)) * APITCH + (lane >> 4) * 16;
    const uint32_t bRow = sb + SB0 + (uint32_t)(wn + (lane & 7) + (lane >> 4) * 8) * APITCH
                        + ((lane >> 3) & 1) * 16;

    float4 xr = *(const float4*)xp;  // chunk 0 prefetch

#pragma unroll 1
    for (int ck = 0; ck < 16; ++ck) {
        // ---- stage A (convert fp32 -> bf16 hi/lo) ----
        __nv_bfloat162 h0 = __floats2bfloat162_rn(xr.x, xr.y);
        __nv_bfloat162 h1 = __floats2bfloat162_rn(xr.z, xr.w);
        float2 r0 = make_float2(xr.x - __bfloat162float(h0.x), xr.y - __bfloat162float(h0.y));
        float2 r1 = make_float2(xr.z - __bfloat162float(h1.x), xr.w - __bfloat162float(h1.y));
        __nv_bfloat162 l0 = __floats2bfloat162_rn(r0.x, r0.y);
        __nv_bfloat162 l1 = __floats2bfloat162_rn(r1.x, r1.y);
        uint2 uh, ul;
        uh.x = *(const uint32_t*)&h0; uh.y = *(const uint32_t*)&h1;
        ul.x = *(const uint32_t*)&l0; ul.y = *(const uint32_t*)&l1;
        *(uint2*)a0s = uh;
        *(uint2*)a1s = ul;
        // ---- stage B (pre-split W, bf16) ----
        *(uint4*)b0s = *(const uint4*)(w0p + ck * 16);
        *(uint4*)b1s = *(const uint4*)(w1p + ck * 16);
        __syncthreads();

        if (ck < 15) xr = *(const float4*)(xp + (ck + 1) * 16);  // prefetch next

        // ---- MMA phase: 3 terms ----
        uint32_t a[4][4], b[2][4];
        // A0 frags
#pragma unroll
        for (int mf = 0; mf < 4; ++mf) ldsm4(a[mf], aRow + mf * 16 * APITCH);
        // term A0*B0
#pragma unroll
        for (int p = 0; p < 2; ++p) ldsm4(b[p], bRow + p * 16 * APITCH);
#pragma unroll
        for (int mf = 0; mf < 4; ++mf)
#pragma unroll
            for (int p = 0; p < 2; ++p) {
                mma16816(c[mf][p * 2],     a[mf], &b[p][0]);
                mma16816(c[mf][p * 2 + 1], a[mf], &b[p][2]);
            }
        // term A0*B1
#pragma unroll
        for (int p = 0; p < 2; ++p) ldsm4(b[p], bRow + 12288 + p * 16 * APITCH);
#pragma unroll
        for (int mf = 0; mf < 4; ++mf)
#pragma unroll
            for (int p = 0; p < 2; ++p) {
                mma16816(c[mf][p * 2],     a[mf], &b[p][0]);
                mma16816(c[mf][p * 2 + 1], a[mf], &b[p][2]);
            }
        // term A1*B0
#pragma unroll
        for (int mf = 0; mf < 4; ++mf) ldsm4(a[mf], aRow + 6144 + mf * 16 * APITCH);
#pragma unroll
        for (int p = 0; p < 2; ++p) ldsm4(b[p], bRow + p * 16 * APITCH);
#pragma unroll
        for (int mf = 0; mf < 4; ++mf)
#pragma unroll
            for (int p = 0; p < 2; ++p) {
                mma16816(c[mf][p * 2],     a[mf], &b[p][0]);
                mma16816(c[mf][p * 2 + 1], a[mf], &b[p][2]);
            }
        __syncthreads();
    }

    // ---- epilogue: bias + store ----
    const float* bp = Bias + gh * 256 + wn + (lane & 3) * 2;
    const int mbase = bx * 128 + wm + (lane >> 2);
    float* gbase = g_gates + (size_t)mbase * 4096 + gh * 256 + wn + (lane & 3) * 2;

#pragma unroll
    for (int nf = 0; nf < 4; ++nf) {
        float2 bv = *(const float2*)(bp + nf * 8);
#pragma unroll
        for (int mf = 0; mf < 4; ++mf) {
            float* p0 = gbase + (size_t)(mf * 16) * 4096 + nf * 8;
            float2 w0 = make_float2(c[mf][nf][0] + bv.x, c[mf][nf][1] + bv.y);
            float2 w1 = make_float2(c[mf][nf][2] + bv.x, c[mf][nf][3] + bv.y);
            *(float2*)p0 = w0;
            *(float2*)(p0 + 8 * 4096) = w1;
        }
    }
}

// ===========================================================================
// Scan phase 1: per-(channel, chunk) local reduction.
// ===========================================================================
__global__ __launch_bounds__(256) void scan_local_kernel()
{
    const int ch = blockIdx.x * 256 + threadIdx.x;  // 0..4095
    const int k  = blockIdx.y;                      // chunk
    const int b  = ch >> 10;
    const int hd = ch & 1023;
    const float* gp = g_gates + (size_t)b * 2048 * 4096 + (size_t)k * CHUNK * 4096 + hd;

    float m = -1e30f, c = 0.f, n = 0.f, F = 0.f;

#pragma unroll
    for (int s = 0; s < CHUNK; ++s) {
        const float* row = gp + (size_t)s * 4096;
        float zb = __ldg(row);
        float ib = __ldg(row + 1024);
        float fb = __ldg(row + 2048);

        float zv = 1.f - __fdividef(2.f, __expf(2.f * zb) + 1.f);

        float lf = fb, li = ib;
        if (fminf(fb, ib) < -6.f) {
            lf = __logf(__expf(fb) + EPSV);
            li = __logf(__expf(ib) + EPSV);
        }
        F += lf;

        float mn = fmaxf(lf + m, li);
        float ih = __expf(li - mn);
        float fh = __expf(lf + m - mn);
        c = fmaf(fh, c, ih * zv);
        n = fmaf(fh, n, ih);
        m = mn;
    }
    g_cstate[(size_t)k * NCH + ch] = make_float4(F, m, c, n);
}

// ===========================================================================
// Scan phase 2: sequential combine over chunks per channel (exact).
// ===========================================================================
__global__ __launch_bounds__(256) void scan_combine_kernel(float* __restrict__ Out)
{
    const int ch = blockIdx.x * 256 + threadIdx.x;  // 0..4095
    float m = 0.f, c = 0.f, n = 0.f;

#pragma unroll 4
    for (int k = 0; k < NCHUNK; ++k) {
        g_carry[(size_t)k * NCH + ch] = make_float4(m, c, n, 0.f);
        float4 st = g_cstate[(size_t)k * NCH + ch];  // (F, m_loc, c_loc, n_loc)
        float mo = fmaxf(st.x + m, st.y);
        float ea = __expf(st.x + m - mo);
        float eb = __expf(st.y - mo);
        c = fmaf(ea, c, eb * st.z);
        n = fmaf(ea, n, eb * st.w);
        m = mo;
    }
    Out[8388608 + 4096 + ch]  = c;   // c_f
    Out[8388608 + 8192 + ch]  = n;   // n_f
    Out[8388608 + 12288 + ch] = m;   // m_f
}

// ===========================================================================
// Scan phase 3: replay each chunk from its exact carry-in and emit h.
// ===========================================================================
__global__ __launch_bounds__(256) void scan_emit_kernel(float* __restrict__ Out)
{
    const int ch = blockIdx.x * 256 + threadIdx.x;
    const int k  = blockIdx.y;
    const int b  = ch >> 10;
    const int hd = ch & 1023;
    const float* gp = g_gates + (size_t)b * 2048 * 4096 + (size_t)k * CHUNK * 4096 + hd;
    float* hp = Out + (size_t)b * 2048 * 1024 + (size_t)k * CHUNK * 1024 + hd;

    float4 cr = g_carry[(size_t)k * NCH + ch];
    float m = cr.x, c = cr.y, n = cr.z, hv = 0.f;

#pragma unroll
    for (int s = 0; s < CHUNK; ++s) {
        const float* row = gp + (size_t)s * 4096;
        float zb = __ldg(row);
        float ib = __ldg(row + 1024);
        float fb = __ldg(row + 2048);
        float ob = __ldg(row + 3072);

        float zv = 1.f - __fdividef(2.f, __expf(2.f * zb) + 1.f);
        float ov = __fdividef(1.f, 1.f + __expf(-ob));

        float lf = fb, li = ib;
        if (fminf(fb, ib) < -6.f) {
            lf = __logf(__expf(fb) + EPSV);
            li = __logf(__expf(ib) + EPSV);
        }

        float mn = fmaxf(lf + m, li);
        float ih = __expf(li - mn);
        float fh = __expf(lf + m - mn);
        c = fmaf(fh, c, ih * zv);
        n = fmaf(fh, n, ih);
        m = mn;
        hv = ov * __fdividef(c, n + EPSV);
        hp[(size_t)s * 1024] = hv;
    }

    if (k == NCHUNK - 1) Out[8388608 + ch] = hv;  // h_f
}

// ---------------------------------------------------------------------------
extern "C" void kernel_launch(void* const* d_in, const int* in_sizes, int n_in,
                              void* d_out, int out_size)
{
    const float* X  = (const float*)d_in[0];  // [4, 2048, 4096]
    const float* W  = (const float*)d_in[1];  // [4, 4, 256, 256]
    const float* Bv = (const float*)d_in[2];  // [4, 4, 256]
    float* out = (float*)d_out;

    wsplit_kernel<<<1024, 256>>>(W);
    gemm_mma_kernel<<<dim3(64, 16), 512>>>(X, Bv);
    scan_local_kernel<<<dim3(16, NCHUNK), 256>>>();
    scan_combine_kernel<<<16, 256>>>(out);
    scan_emit_kernel<<<dim3(16, NCHUNK), 256>>>(out);
}

// round 7
// speedup vs baseline: 3.2842x; 1.1558x over previous
#include <cuda_runtime.h>
#include <cuda_bf16.h>
#include <cstdint>
#include <cstddef>

#define EPSV 1e-8f
#define CHUNK 64
#define NCHUNK 32
#define NCH 4096  // channels = B*NH*HD

// Gate pre-activations scratch: [B=4][S=2048][4 gates][NH=4][HD=256] fp32 = 128 MiB
static __device__ float g_gates[33554432];
// per-(chunk,channel) local state (F, m_loc, c_loc, n_loc)
static __device__ float4 g_cstate[NCHUNK * NCH];
// per-(chunk,channel) carry-in state (m, c, n, -)
static __device__ float4 g_carry[NCHUNK * NCH];
// Pre-split weights: bf16 hi/lo, layout [gh][n][k] like W
static __device__ __nv_bfloat16 g_W0[1048576];
static __device__ __nv_bfloat16 g_W1[1048576];

// ---------------------------------------------------------------------------
__device__ __forceinline__ uint32_t smem_u32(const void* p) {
    uint32_t a;
    asm("{ .reg .u64 t; cvta.to.shared.u64 t, %1; cvt.u32.u64 %0, t; }" : "=r"(a) : "l"(p));
    return a;
}
__device__ __forceinline__ void ldsm4(uint32_t* r, uint32_t addr) {
    asm volatile("ldmatrix.sync.aligned.m8n8.x4.shared.b16 {%0,%1,%2,%3}, [%4];"
                 : "=r"(r[0]), "=r"(r[1]), "=r"(r[2]), "=r"(r[3]) : "r"(addr));
}
__device__ __forceinline__ void mma16816(float* c, const uint32_t* a, const uint32_t* b) {
    asm volatile(
        "mma.sync.aligned.m16n8k16.row.col.f32.bf16.bf16.f32 "
        "{%0,%1,%2,%3}, {%4,%5,%6,%7}, {%8,%9}, {%0,%1,%2,%3};"
        : "+f"(c[0]), "+f"(c[1]), "+f"(c[2]), "+f"(c[3])
        : "r"(a[0]), "r"(a[1]), "r"(a[2]), "r"(a[3]), "r"(b[0]), "r"(b[1]));
}

// ===========================================================================
// Kernel 0: pre-split W (fp32 -> bf16 hi + bf16 lo). 1,048,576 elements.
// ===========================================================================
__global__ __launch_bounds__(256) void wsplit_kernel(const float* __restrict__ W)
{
    const int i = blockIdx.x * 256 + threadIdx.x;  // float4 id, 262144 total
    float4 v = *(const float4*)(W + (size_t)i * 4);
    __nv_bfloat162 h0 = __floats2bfloat162_rn(v.x, v.y);
    __nv_bfloat162 h1 = __floats2bfloat162_rn(v.z, v.w);
    float2 r0 = make_float2(v.x - __bfloat162float(h0.x), v.y - __bfloat162float(h0.y));
    float2 r1 = make_float2(v.z - __bfloat162float(h1.x), v.w - __bfloat162float(h1.y));
    __nv_bfloat162 l0 = __floats2bfloat162_rn(r0.x, r0.y);
    __nv_bfloat162 l1 = __floats2bfloat162_rn(r1.x, r1.y);
    uint2 uh, ul;
    uh.x = *(const uint32_t*)&h0; uh.y = *(const uint32_t*)&h1;
    ul.x = *(const uint32_t*)&l0; ul.y = *(const uint32_t*)&l1;
    *(uint2*)&g_W0[(size_t)i * 4] = uh;
    *(uint2*)&g_W1[(size_t)i * 4] = ul;
}

// ===========================================================================
// Kernel 1: block-diagonal GEMM via mma.sync bf16 (3-term 2-split),
//   double-buffered smem staging overlapped with MMA.
//   grid (64 m-tiles, 16 gh), 512 threads = 16 warps (2 m x 8 n),
//   warp tile 64x32. K=256 in 16 chunks of 16.
//   smem rows: 16 bf16 data + 8 pad = 48B row pitch (conflict-free ldmatrix).
// ===========================================================================
#define APITCH 48       // bytes per A/B smem row (16 bf16 + 8 pad)
#define SA0 0           // 128 rows * 48B = 6144
#define SA1 6144
#define SB0 12288       // 256 rows * 48B = 12288
#define SB1 24576
#define BUFSZ 36864
#define SMEM_GEMM (2 * BUFSZ)

__global__ __launch_bounds__(512) void gemm_mma_kernel(
    const float* __restrict__ X, const float* __restrict__ Bias)
{
    extern __shared__ __align__(16) char smem[];
    const uint32_t sb = smem_u32(smem);

    const int tid  = threadIdx.x;
    const int lane = tid & 31;
    const int wid  = tid >> 5;
    const int wm   = (wid & 1) * 64;   // warp m offset
    const int wn   = (wid >> 1) * 32;  // warp n offset
    const int bx   = blockIdx.x;
    const int gh   = blockIdx.y;

    float c[4][4][4];
#pragma unroll
    for (int i = 0; i < 4; ++i)
#pragma unroll
        for (int j = 0; j < 4; ++j)
#pragma unroll
            for (int q = 0; q < 4; ++q) c[i][j][q] = 0.f;

    // staging pointers (per-thread)
    const float* xp = X + (size_t)(bx * 128 + (tid >> 2)) * 4096 + gh * 256 + (tid & 3) * 4;
    const __nv_bfloat16* w0p = g_W0 + (size_t)gh * 65536 + (size_t)(tid >> 1) * 256 + (tid & 1) * 8;
    const __nv_bfloat16* w1p = g_W1 + (size_t)gh * 65536 + (size_t)(tid >> 1) * 256 + (tid & 1) * 8;

    const uint32_t a0off = SA0 + (uint32_t)(tid >> 2) * APITCH + (tid & 3) * 8;
    const uint32_t a1off = SA1 + (uint32_t)(tid >> 2) * APITCH + (tid & 3) * 8;
    const uint32_t b0off = SB0 + (uint32_t)(tid >> 1) * APITCH + (tid & 1) * 16;
    const uint32_t b1off = SB1 + (uint32_t)(tid >> 1) * APITCH + (tid & 1) * 16;

    // ldmatrix base offsets (within a buffer)
    const uint32_t aRowOff = SA0 + (uint32_t)(wm + (lane & 15)) * APITCH + (lane >> 4) * 16;
    const uint32_t bRowOff = SB0 + (uint32_t)(wn + (lane & 7) + (lane >> 4) * 8) * APITCH
                           + ((lane >> 3) & 1) * 16;

    // ---- prologue: stage chunk 0 into buffer 0 ----
    float4 xr = *(const float4*)xp;
    uint4 w0r = *(const uint4*)w0p;
    uint4 w1r = *(const uint4*)w1p;
    {
        __nv_bfloat162 h0 = __floats2bfloat162_rn(xr.x, xr.y);
        __nv_bfloat162 h1 = __floats2bfloat162_rn(xr.z, xr.w);
        float2 r0 = make_float2(xr.x - __bfloat162float(h0.x), xr.y - __bfloat162float(h0.y));
        float2 r1 = make_float2(xr.z - __bfloat162float(h1.x), xr.w - __bfloat162float(h1.y));
        __nv_bfloat162 l0 = __floats2bfloat162_rn(r0.x, r0.y);
        __nv_bfloat162 l1 = __floats2bfloat162_rn(r1.x, r1.y);
        uint2 uh, ul;
        uh.x = *(const uint32_t*)&h0; uh.y = *(const uint32_t*)&h1;
        ul.x = *(const uint32_t*)&l0; ul.y = *(const uint32_t*)&l1;
        *(uint2*)(smem + a0off) = uh;
        *(uint2*)(smem + a1off) = ul;
        *(uint4*)(smem + b0off) = w0r;
        *(uint4*)(smem + b1off) = w1r;
    }
    __syncthreads();

#pragma unroll 1
    for (int ck = 0; ck < 16; ++ck) {
        const uint32_t bufS = (uint32_t)(ck & 1) * BUFSZ;        // smem-addr base (ldsm)
        const uint32_t bufN = (uint32_t)((ck + 1) & 1) * BUFSZ;  // next buffer (stores)

        // ---- issue global prefetch for chunk ck+1 as early as possible ----
        if (ck < 15) {
            xr  = *(const float4*)(xp + (ck + 1) * 16);
            w0r = *(const uint4*)(w0p + (ck + 1) * 16);
            w1r = *(const uint4*)(w1p + (ck + 1) * 16);
        }

        // ---- MMA phase on current buffer ----
        const uint32_t aRow = sb + bufS + aRowOff;
        const uint32_t bRow = sb + bufS + bRowOff;
        uint32_t a[4][4], b[2][4];
        // A0 frags
#pragma unroll
        for (int mf = 0; mf < 4; ++mf) ldsm4(a[mf], aRow + mf * 16 * APITCH);
        // term A0*B0
#pragma unroll
        for (int p = 0; p < 2; ++p) ldsm4(b[p], bRow + p * 16 * APITCH);
#pragma unroll
        for (int mf = 0; mf < 4; ++mf)
#pragma unroll
            for (int p = 0; p < 2; ++p) {
                mma16816(c[mf][p * 2],     a[mf], &b[p][0]);
                mma16816(c[mf][p * 2 + 1], a[mf], &b[p][2]);
            }
        // term A0*B1
#pragma unroll
        for (int p = 0; p < 2; ++p) ldsm4(b[p], bRow + 12288 + p * 16 * APITCH);
#pragma unroll
        for (int mf = 0; mf < 4; ++mf)
#pragma unroll
            for (int p = 0; p < 2; ++p) {
                mma16816(c[mf][p * 2],     a[mf], &b[p][0]);
                mma16816(c[mf][p * 2 + 1], a[mf], &b[p][2]);
            }
        // term A1*B0
#pragma unroll
        for (int mf = 0; mf < 4; ++mf) ldsm4(a[mf], aRow + 6144 + mf * 16 * APITCH);
#pragma unroll
        for (int p = 0; p < 2; ++p) ldsm4(b[p], bRow + p * 16 * APITCH);
#pragma unroll
        for (int mf = 0; mf < 4; ++mf)
#pragma unroll
            for (int p = 0; p < 2; ++p) {
                mma16816(c[mf][p * 2],     a[mf], &b[p][0]);
                mma16816(c[mf][p * 2 + 1], a[mf], &b[p][2]);
            }

        // ---- stage chunk ck+1 into next buffer (overlaps with other warps' MMAs) ----
        if (ck < 15) {
            __nv_bfloat162 h0 = __floats2bfloat162_rn(xr.x, xr.y);
            __nv_bfloat162 h1 = __floats2bfloat162_rn(xr.z, xr.w);
            float2 r0 = make_float2(xr.x - __bfloat162float(h0.x), xr.y - __bfloat162float(h0.y));
            float2 r1 = make_float2(xr.z - __bfloat162float(h1.x), xr.w - __bfloat162float(h1.y));
            __nv_bfloat162 l0 = __floats2bfloat162_rn(r0.x, r0.y);
            __nv_bfloat162 l1 = __floats2bfloat162_rn(r1.x, r1.y);
            uint2 uh, ul;
            uh.x = *(const uint32_t*)&h0; uh.y = *(const uint32_t*)&h1;
            ul.x = *(const uint32_t*)&l0; ul.y = *(const uint32_t*)&l1;
            *(uint2*)(smem + bufN + a0off) = uh;
            *(uint2*)(smem + bufN + a1off) = ul;
            *(uint4*)(smem + bufN + b0off) = w0r;
            *(uint4*)(smem + bufN + b1off) = w1r;
        }
        __syncthreads();
    }

    // ---- epilogue: bias + store ----
    const float* bp = Bias + gh * 256 + wn + (lane & 3) * 2;
    const int mbase = bx * 128 + wm + (lane >> 2);
    float* gbase = g_gates + (size_t)mbase * 4096 + gh * 256 + wn + (lane & 3) * 2;

#pragma unroll
    for (int nf = 0; nf < 4; ++nf) {
        float2 bv = *(const float2*)(bp + nf * 8);
#pragma unroll
        for (int mf = 0; mf < 4; ++mf) {
            float* p0 = gbase + (size_t)(mf * 16) * 4096 + nf * 8;
            float2 w0 = make_float2(c[mf][nf][0] + bv.x, c[mf][nf][1] + bv.y);
            float2 w1 = make_float2(c[mf][nf][2] + bv.x, c[mf][nf][3] + bv.y);
            *(float2*)p0 = w0;
            *(float2*)(p0 + 8 * 4096) = w1;
        }
    }
}

// ===========================================================================
// Scan phase 1: per-(channel, chunk) local reduction. CHUNK=64, NCHUNK=32.
// ===========================================================================
__global__ __launch_bounds__(256) void scan_local_kernel()
{
    const int ch = blockIdx.x * 256 + threadIdx.x;  // 0..4095
    const int k  = blockIdx.y;                      // chunk
    const int b  = ch >> 10;
    const int hd = ch & 1023;
    const float* gp = g_gates + (size_t)b * 2048 * 4096 + (size_t)k * CHUNK * 4096 + hd;

    float m = -1e30f, c = 0.f, n = 0.f, F = 0.f;

#pragma unroll 8
    for (int s = 0; s < CHUNK; ++s) {
        const float* row = gp + (size_t)s * 4096;
        float zb = __ldg(row);
        float ib = __ldg(row + 1024);
        float fb = __ldg(row + 2048);

        float zv = 1.f - __fdividef(2.f, __expf(2.f * zb) + 1.f);

        float lf = fb, li = ib;
        if (fminf(fb, ib) < -6.f) {
            lf = __logf(__expf(fb) + EPSV);
            li = __logf(__expf(ib) + EPSV);
        }
        F += lf;

        float mn = fmaxf(lf + m, li);
        float ih = __expf(li - mn);
        float fh = __expf(lf + m - mn);
        c = fmaf(fh, c, ih * zv);
        n = fmaf(fh, n, ih);
        m = mn;
    }
    g_cstate[(size_t)k * NCH + ch] = make_float4(F, m, c, n);
}

// ===========================================================================
// Scan phase 2: sequential combine over 32 chunks per channel, with explicit
// batch-of-8 register prefetch (MLP=8 instead of dependent MLP=1 chain).
// ===========================================================================
__global__ __launch_bounds__(256) void scan_combine_kernel(float* __restrict__ Out)
{
    const int ch = blockIdx.x * 256 + threadIdx.x;  // 0..4095
    float m = 0.f, c = 0.f, n = 0.f;

#pragma unroll 1
    for (int k0 = 0; k0 < NCHUNK; k0 += 8) {
        float4 buf[8];
#pragma unroll
        for (int j = 0; j < 8; ++j)
            buf[j] = g_cstate[(size_t)(k0 + j) * NCH + ch];
#pragma unroll
        for (int j = 0; j < 8; ++j) {
            g_carry[(size_t)(k0 + j) * NCH + ch] = make_float4(m, c, n, 0.f);
            float4 st = buf[j];  // (F, m_loc, c_loc, n_loc)
            float mo = fmaxf(st.x + m, st.y);
            float ea = __expf(st.x + m - mo);
            float eb = __expf(st.y - mo);
            c = fmaf(ea, c, eb * st.z);
            n = fmaf(ea, n, eb * st.w);
            m = mo;
        }
    }
    Out[8388608 + 4096 + ch]  = c;   // c_f
    Out[8388608 + 8192 + ch]  = n;   // n_f
    Out[8388608 + 12288 + ch] = m;   // m_f
}

// ===========================================================================
// Scan phase 3: replay each chunk from its exact carry-in and emit h.
// ===========================================================================
__global__ __launch_bounds__(256) void scan_emit_kernel(float* __restrict__ Out)
{
    const int ch = blockIdx.x * 256 + threadIdx.x;
    const int k  = blockIdx.y;
    const int b  = ch >> 10;
    const int hd = ch & 1023;
    const float* gp = g_gates + (size_t)b * 2048 * 4096 + (size_t)k * CHUNK * 4096 + hd;
    float* hp = Out + (size_t)b * 2048 * 1024 + (size_t)k * CHUNK * 1024 + hd;

    float4 cr = g_carry[(size_t)k * NCH + ch];
    float m = cr.x, c = cr.y, n = cr.z, hv = 0.f;

#pragma unroll 8
    for (int s = 0; s < CHUNK; ++s) {
        const float* row = gp + (size_t)s * 4096;
        float zb = __ldg(row);
        float ib = __ldg(row + 1024);
        float fb = __ldg(row + 2048);
        float ob = __ldg(row + 3072);

        float zv = 1.f - __fdividef(2.f, __expf(2.f * zb) + 1.f);
        float ov = __fdividef(1.f, 1.f + __expf(-ob));

        float lf = fb, li = ib;
        if (fminf(fb, ib) < -6.f) {
            lf = __logf(__expf(fb) + EPSV);
            li = __logf(__expf(ib) + EPSV);
        }

        float mn = fmaxf(lf + m, li);
        float ih = __expf(li - mn);
        float fh = __expf(lf + m - mn);
        c = fmaf(fh, c, ih * zv);
        n = fmaf(fh, n, ih);
        m = mn;
        hv = ov * __fdividef(c, n + EPSV);
        hp[(size_t)s * 1024] = hv;
    }

    if (k == NCHUNK - 1) Out[8388608 + ch] = hv;  // h_f
}

// ---------------------------------------------------------------------------
extern "C" void kernel_launch(void* const* d_in, const int* in_sizes, int n_in,
                              void* d_out, int out_size)
{
    const float* X  = (const float*)d_in[0];  // [4, 2048, 4096]
    const float* W  = (const float*)d_in[1];  // [4, 4, 256, 256]
    const float* Bv = (const float*)d_in[2];  // [4, 4, 256]
    float* out = (float*)d_out;

    cudaFuncSetAttribute(gemm_mma_kernel, cudaFuncAttributeMaxDynamicSharedMemorySize,
                         SMEM_GEMM);

    wsplit_kernel<<<1024, 256>>>(W);
    gemm_mma_kernel<<<dim3(64, 16), 512, SMEM_GEMM>>>(X, Bv);
    scan_local_kernel<<<dim3(16, NCHUNK), 256>>>();
    scan_combine_kernel<<<16, 256>>>(out);
    scan_emit_kernel<<<dim3(16, NCHUNK), 256>>>(out);
}

// round 9
// speedup vs baseline: 3.6692x; 1.1172x over previous
#include <cuda_runtime.h>
#include <cuda_bf16.h>
#include <cstdint>
#include <cstddef>

#define EPSV 1e-8f
#define CHUNK 64
#define NCHUNK 32
#define NCH 4096  // channels = B*NH*HD

// Gate pre-activations scratch: [B=4][S=2048][4 gates][NH=4][HD=256] fp32 = 128 MiB
static __device__ float g_gates[33554432];
// per-(chunk,channel) local state (F, m_loc, c_loc, n_loc)
static __device__ float4 g_cstate[NCHUNK * NCH];
// per-(chunk,channel) carry-in state (m, c, n, -)
static __device__ float4 g_carry[NCHUNK * NCH];
// Pre-split weights: bf16 hi/lo, layout [gh][n][k] like W
static __device__ __nv_bfloat16 g_W0[1048576];
static __device__ __nv_bfloat16 g_W1[1048576];

// ---------------------------------------------------------------------------
__device__ __forceinline__ uint32_t smem_u32(const void* p) {
    uint32_t a;
    asm("{ .reg .u64 t; cvta.to.shared.u64 t, %1; cvt.u32.u64 %0, t; }" : "=r"(a) : "l"(p));
    return a;
}
__device__ __forceinline__ void ldsm4(uint32_t* r, uint32_t addr) {
    asm volatile("ldmatrix.sync.aligned.m8n8.x4.shared.b16 {%0,%1,%2,%3}, [%4];"
                 : "=r"(r[0]), "=r"(r[1]), "=r"(r[2]), "=r"(r[3]) : "r"(addr));
}
__device__ __forceinline__ void mma16816(float* c, const uint32_t* a, const uint32_t* b) {
    asm volatile(
        "mma.sync.aligned.m16n8k16.row.col.f32.bf16.bf16.f32 "
        "{%0,%1,%2,%3}, {%4,%5,%6,%7}, {%8,%9}, {%0,%1,%2,%3};"
        : "+f"(c[0]), "+f"(c[1]), "+f"(c[2]), "+f"(c[3])
        : "r"(a[0]), "r"(a[1]), "r"(a[2]), "r"(a[3]), "r"(b[0]), "r"(b[1]));
}
#define CP_ASYNC16(sa, gp) \
    asm volatile("cp.async.ca.shared.global [%0], [%1], 16;" :: "r"(sa), "l"(gp))
#define CP_COMMIT() asm volatile("cp.async.commit_group;" ::: "memory")
#define CP_WAIT0()  asm volatile("cp.async.wait_group 0;" ::: "memory")

// convert 8 fp32 -> bf16 hi (uint2 x2) + lo (uint2 x2)
__device__ __forceinline__ void split8(const float4& v0, const float4& v1,
                                       uint2& h_a, uint2& h_b, uint2& l_a, uint2& l_b) {
    __nv_bfloat162 h0 = __floats2bfloat162_rn(v0.x, v0.y);
    __nv_bfloat162 h1 = __floats2bfloat162_rn(v0.z, v0.w);
    __nv_bfloat162 h2 = __floats2bfloat162_rn(v1.x, v1.y);
    __nv_bfloat162 h3 = __floats2bfloat162_rn(v1.z, v1.w);
    __nv_bfloat162 l0 = __floats2bfloat162_rn(v0.x - __bfloat162float(h0.x), v0.y - __bfloat162float(h0.y));
    __nv_bfloat162 l1 = __floats2bfloat162_rn(v0.z - __bfloat162float(h1.x), v0.w - __bfloat162float(h1.y));
    __nv_bfloat162 l2 = __floats2bfloat162_rn(v1.x - __bfloat162float(h2.x), v1.y - __bfloat162float(h2.y));
    __nv_bfloat162 l3 = __floats2bfloat162_rn(v1.z - __bfloat162float(h3.x), v1.w - __bfloat162float(h3.y));
    h_a.x = *(const uint32_t*)&h0; h_a.y = *(const uint32_t*)&h1;
    h_b.x = *(const uint32_t*)&h2; h_b.y = *(const uint32_t*)&h3;
    l_a.x = *(const uint32_t*)&l0; l_a.y = *(const uint32_t*)&l1;
    l_b.x = *(const uint32_t*)&l2; l_b.y = *(const uint32_t*)&l3;
}

// ===========================================================================
// Kernel 0: pre-split W (fp32 -> bf16 hi + bf16 lo). 1,048,576 elements.
// ===========================================================================
__global__ __launch_bounds__(256) void wsplit_kernel(const float* __restrict__ W)
{
    const int i = blockIdx.x * 256 + threadIdx.x;  // float4 id, 262144 total
    float4 v = *(const float4*)(W + (size_t)i * 4);
    uint2 ha, hb, la, lb;
    float4 dummy = make_float4(0.f, 0.f, 0.f, 0.f);
    (void)dummy;
    __nv_bfloat162 h0 = __floats2bfloat162_rn(v.x, v.y);
    __nv_bfloat162 h1 = __floats2bfloat162_rn(v.z, v.w);
    __nv_bfloat162 l0 = __floats2bfloat162_rn(v.x - __bfloat162float(h0.x), v.y - __bfloat162float(h0.y));
    __nv_bfloat162 l1 = __floats2bfloat162_rn(v.z - __bfloat162float(h1.x), v.w - __bfloat162float(h1.y));
    ha.x = *(const uint32_t*)&h0; ha.y = *(const uint32_t*)&h1;
    la.x = *(const uint32_t*)&l0; la.y = *(const uint32_t*)&l1;
    (void)hb; (void)lb;
    *(uint2*)&g_W0[(size_t)i * 4] = ha;
    *(uint2*)&g_W1[(size_t)i * 4] = la;
}

// ===========================================================================
// Kernel 1: block-diagonal GEMM via mma.sync bf16 (3-term 2-split)
//   grid (64 m-tiles, 16 gh), 512 threads = 16 warps (2 m x 8 n),
//   warp tile 64x32. K=256 in 8 chunks of 32.
//   A: LDG->convert->STS double-buffered. B: cp.async double-buffered.
//   smem rows: 32 bf16 (64B) + 16B pad = 80B pitch (conflict-free ldmatrix).
// ===========================================================================
#define APITCH 80
#define SA0 0            // 128 rows * 80B = 10240
#define SA1 10240
#define SB0 20480        // 256 rows * 80B = 20480
#define SB1 40960
#define BUFSZ 61440
#define SMEM_GEMM (2 * BUFSZ)

__global__ __launch_bounds__(512) void gemm_mma_kernel(
    const float* __restrict__ X, const float* __restrict__ Bias)
{
    extern __shared__ __align__(16) char smem[];
    const uint32_t sb = smem_u32(smem);

    const int tid  = threadIdx.x;
    const int lane = tid & 31;
    const int wid  = tid >> 5;
    const int wm   = (wid & 1) * 64;   // warp m offset
    const int wn   = (wid >> 1) * 32;  // warp n offset
    const int bx   = blockIdx.x;
    const int gh   = blockIdx.y;

    float c[4][4][4];
#pragma unroll
    for (int i = 0; i < 4; ++i)
#pragma unroll
        for (int j = 0; j < 4; ++j)
#pragma unroll
            for (int q = 0; q < 4; ++q) c[i][j][q] = 0.f;

    // ---- staging assignments ----
    // A: thread -> row (tid>>2) [0..127], col group (tid&3)*8 floats of 32
    const float* xp = X + (size_t)(bx * 128 + (tid >> 2)) * 4096 + gh * 256 + (tid & 3) * 8;
    const uint32_t aSt0 = (uint32_t)(tid >> 2) * APITCH + (tid & 3) * 16;  // bf16: 8 elems=16B
    // B: thread -> row (tid>>1) [0..255], 32B half (tid&1)
    const __nv_bfloat16* w0p = g_W0 + (size_t)gh * 65536 + (size_t)(tid >> 1) * 256 + (tid & 1) * 16;
    const __nv_bfloat16* w1p = g_W1 + (size_t)gh * 65536 + (size_t)(tid >> 1) * 256 + (tid & 1) * 16;
    const uint32_t bSt = (uint32_t)(tid >> 1) * APITCH + (tid & 1) * 32;

    // ldmatrix base offsets (within a buffer)
    const uint32_t aRowOff = SA0 + (uint32_t)(wm + (lane & 15)) * APITCH + (lane >> 4) * 16;
    const uint32_t bRowOff = SB0 + (uint32_t)(wn + (lane & 7) + (lane >> 4) * 8) * APITCH
                           + ((lane >> 3) & 1) * 16;

    // ---- prologue: stage chunk 0 into buffer 0 ----
    {
        float4 v0 = *(const float4*)xp;
        float4 v1 = *(const float4*)(xp + 4);
        uint2 ha, hb, la, lb;
        split8(v0, v1, ha, hb, la, lb);
        *(uint2*)(smem + SA0 + aSt0) = ha;
        *(uint2*)(smem + SA0 + aSt0 + 8) = hb;
        *(uint2*)(smem + SA1 + aSt0) = la;
        *(uint2*)(smem + SA1 + aSt0 + 8) = lb;
        CP_ASYNC16(sb + SB0 + bSt,      w0p);
        CP_ASYNC16(sb + SB0 + bSt + 16, w0p + 8);
        CP_ASYNC16(sb + SB1 + bSt,      w1p);
        CP_ASYNC16(sb + SB1 + bSt + 16, w1p + 8);
        CP_COMMIT();
    }
    CP_WAIT0();
    __syncthreads();

#pragma unroll 1
    for (int ck = 0; ck < 8; ++ck) {
        const uint32_t bufS = (uint32_t)(ck & 1) * BUFSZ;
        const uint32_t bufN = (uint32_t)((ck + 1) & 1) * BUFSZ;

        float4 v0, v1;
        if (ck < 7) {
            // issue next-chunk loads early
            v0 = *(const float4*)(xp + (ck + 1) * 32);
            v1 = *(const float4*)(xp + (ck + 1) * 32 + 4);
            CP_ASYNC16(sb + bufN + SB0 + bSt,      w0p + (ck + 1) * 32);
            CP_ASYNC16(sb + bufN + SB0 + bSt + 16, w0p + (ck + 1) * 32 + 8);
            CP_ASYNC16(sb + bufN + SB1 + bSt,      w1p + (ck + 1) * 32);
            CP_ASYNC16(sb + bufN + SB1 + bSt + 16, w1p + (ck + 1) * 32 + 8);
            CP_COMMIT();
        }

        // ---- MMA phase on current buffer: 2 k16 subchunks x 3 terms ----
        const uint32_t aRow = sb + bufS + aRowOff;
        const uint32_t bRow = sb + bufS + bRowOff;
#pragma unroll
        for (int s = 0; s < 2; ++s) {
            const uint32_t acol = (uint32_t)s * 32;
            uint32_t a[4][4], b[2][4];
            // A0 frags
#pragma unroll
            for (int mf = 0; mf < 4; ++mf) ldsm4(a[mf], aRow + acol + mf * 16 * APITCH);
            // term A0*B0
#pragma unroll
            for (int p = 0; p < 2; ++p) ldsm4(b[p], bRow + acol + p * 16 * APITCH);
#pragma unroll
            for (int mf = 0; mf < 4; ++mf)
#pragma unroll
                for (int p = 0; p < 2; ++p) {
                    mma16816(c[mf][p * 2],     a[mf], &b[p][0]);
                    mma16816(c[mf][p * 2 + 1], a[mf], &b[p][2]);
                }
            // term A0*B1
#pragma unroll
            for (int p = 0; p < 2; ++p) ldsm4(b[p], bRow + 20480 + acol + p * 16 * APITCH);
#pragma unroll
            for (int mf = 0; mf < 4; ++mf)
#pragma unroll
                for (int p = 0; p < 2; ++p) {
                    mma16816(c[mf][p * 2],     a[mf], &b[p][0]);
                    mma16816(c[mf][p * 2 + 1], a[mf], &b[p][2]);
                }
            // term A1*B0
#pragma unroll
            for (int mf = 0; mf < 4; ++mf) ldsm4(a[mf], aRow + 10240 + acol + mf * 16 * APITCH);
#pragma unroll
            for (int p = 0; p < 2; ++p) ldsm4(b[p], bRow + acol + p * 16 * APITCH);
#pragma unroll
            for (int mf = 0; mf < 4; ++mf)
#pragma unroll
                for (int p = 0; p < 2; ++p) {
                    mma16816(c[mf][p * 2],     a[mf], &b[p][0]);
                    mma16816(c[mf][p * 2 + 1], a[mf], &b[p][2]);
                }
        }

        // ---- stage A for next chunk into next buffer ----
        if (ck < 7) {
            uint2 ha, hb, la, lb;
            split8(v0, v1, ha, hb, la, lb);
            *(uint2*)(smem + bufN + SA0 + aSt0) = ha;
            *(uint2*)(smem + bufN + SA0 + aSt0 + 8) = hb;
            *(uint2*)(smem + bufN + SA1 + aSt0) = la;
            *(uint2*)(smem + bufN + SA1 + aSt0 + 8) = lb;
        }
        CP_WAIT0();
        __syncthreads();
    }

    // ---- epilogue: bias + store ----
    const float* bp = Bias + gh * 256 + wn + (lane & 3) * 2;
    const int mbase = bx * 128 + wm + (lane >> 2);
    float* gbase = g_gates + (size_t)mbase * 4096 + gh * 256 + wn + (lane & 3) * 2;

#pragma unroll
    for (int nf = 0; nf < 4; ++nf) {
        float2 bv = *(const float2*)(bp + nf * 8);
#pragma unroll
        for (int mf = 0; mf < 4; ++mf) {
            float* p0 = gbase + (size_t)(mf * 16) * 4096 + nf * 8;
            float2 w0 = make_float2(c[mf][nf][0] + bv.x, c[mf][nf][1] + bv.y);
            float2 w1 = make_float2(c[mf][nf][2] + bv.x, c[mf][nf][3] + bv.y);
            *(float2*)p0 = w0;
            *(float2*)(p0 + 8 * 4096) = w1;
        }
    }
}

// ===========================================================================
// Scan phase 1: per-(channel, chunk) local reduction. CHUNK=64, NCHUNK=32.
// ===========================================================================
__global__ __launch_bounds__(256) void scan_local_kernel()
{
    const int ch = blockIdx.x * 256 + threadIdx.x;  // 0..4095
    const int k  = blockIdx.y;                      // chunk
    const int b  = ch >> 10;
    const int hd = ch & 1023;
    const float* gp = g_gates + (size_t)b * 2048 * 4096 + (size_t)k * CHUNK * 4096 + hd;

    float m = -1e30f, c = 0.f, n = 0.f, F = 0.f;

#pragma unroll 8
    for (int s = 0; s < CHUNK; ++s) {
        const float* row = gp + (size_t)s * 4096;
        float zb = __ldg(row);
        float ib = __ldg(row + 1024);
        float fb = __ldg(row + 2048);

        float zv = 1.f - __fdividef(2.f, __expf(2.f * zb) + 1.f);

        float lf = fb, li = ib;
        if (fminf(fb, ib) < -6.f) {
            lf = __logf(__expf(fb) + EPSV);
            li = __logf(__expf(ib) + EPSV);
        }
        F += lf;

        float mn = fmaxf(lf + m, li);
        float ih = __expf(li - mn);
        float fh = __expf(lf + m - mn);
        c = fmaf(fh, c, ih * zv);
        n = fmaf(fh, n, ih);
        m = mn;
    }
    g_cstate[(size_t)k * NCH + ch] = make_float4(F, m, c, n);
}

// ===========================================================================
// Scan phase 2: sequential combine with batch-of-8 register prefetch.
// ===========================================================================
__global__ __launch_bounds__(256) void scan_combine_kernel(float* __restrict__ Out)
{
    const int ch = blockIdx.x * 256 + threadIdx.x;  // 0..4095
    float m = 0.f, c = 0.f, n = 0.f;

#pragma unroll 1
    for (int k0 = 0; k0 < NCHUNK; k0 += 8) {
        float4 buf[8];
#pragma unroll
        for (int j = 0; j < 8; ++j)
            buf[j] = g_cstate[(size_t)(k0 + j) * NCH + ch];
#pragma unroll
        for (int j = 0; j < 8; ++j) {
            g_carry[(size_t)(k0 + j) * NCH + ch] = make_float4(m, c, n, 0.f);
            float4 st = buf[j];  // (F, m_loc, c_loc, n_loc)
            float mo = fmaxf(st.x + m, st.y);
            float ea = __expf(st.x + m - mo);
            float eb = __expf(st.y - mo);
            c = fmaf(ea, c, eb * st.z);
            n = fmaf(ea, n, eb * st.w);
            m = mo;
        }
    }
    Out[8388608 + 4096 + ch]  = c;   // c_f
    Out[8388608 + 8192 + ch]  = n;   // n_f
    Out[8388608 + 12288 + ch] = m;   // m_f
}

// ===========================================================================
// Scan phase 3: replay each chunk from its exact carry-in and emit h.
// ===========================================================================
__global__ __launch_bounds__(256) void scan_emit_kernel(float* __restrict__ Out)
{
    const int ch = blockIdx.x * 256 + threadIdx.x;
    const int k  = blockIdx.y;
    const int b  = ch >> 10;
    const int hd = ch & 1023;
    const float* gp = g_gates + (size_t)b * 2048 * 4096 + (size_t)k * CHUNK * 4096 + hd;
    float* hp = Out + (size_t)b * 2048 * 1024 + (size_t)k * CHUNK * 1024 + hd;

    float4 cr = g_carry[(size_t)k * NCH + ch];
    float m = cr.x, c = cr.y, n = cr.z, hv = 0.f;

#pragma unroll 8
    for (int s = 0; s < CHUNK; ++s) {
        const float* row = gp + (size_t)s * 4096;
        float zb = __ldg(row);
        float ib = __ldg(row + 1024);
        float fb = __ldg(row + 2048);
        float ob = __ldg(row + 3072);

        float zv = 1.f - __fdividef(2.f, __expf(2.f * zb) + 1.f);
        float ov = __fdividef(1.f, 1.f + __expf(-ob));

        float lf = fb, li = ib;
        if (fminf(fb, ib) < -6.f) {
            lf = __logf(__expf(fb) + EPSV);
            li = __logf(__expf(ib) + EPSV);
        }

        float mn = fmaxf(lf + m, li);
        float ih = __expf(li - mn);
        float fh = __expf(lf + m - mn);
        c = fmaf(fh, c, ih * zv);
        n = fmaf(fh, n, ih);
        m = mn;
        hv = ov * __fdividef(c, n + EPSV);
        hp[(size_t)s * 1024] = hv;
    }

    if (k == NCHUNK - 1) Out[8388608 + ch] = hv;  // h_f
}

// ---------------------------------------------------------------------------
extern "C" void kernel_launch(void* const* d_in, const int* in_sizes, int n_in,
                              void* d_out, int out_size)
{
    const float* X  = (const float*)d_in[0];  // [4, 2048, 4096]
    const float* W  = (const float*)d_in[1];  // [4, 4, 256, 256]
    const float* Bv = (const float*)d_in[2];  // [4, 4, 256]
    float* out = (float*)d_out;

    cudaFuncSetAttribute(gemm_mma_kernel, cudaFuncAttributeMaxDynamicSharedMemorySize,
                         SMEM_GEMM);

    wsplit_kernel<<<1024, 256>>>(W);
    gemm_mma_kernel<<<dim3(64, 16), 512, SMEM_GEMM>>>(X, Bv);
    scan_local_kernel<<<dim3(16, NCHUNK), 256>>>();
    scan_combine_kernel<<<16, 256>>>(out);
    scan_emit_kernel<<<dim3(16, NCHUNK), 256>>>(out);
}